// round 9
// baseline (speedup 1.0000x reference)
#include <cuda_runtime.h>
#include <math.h>

#define BQ      256      // batch (queries)
#define D       512      // embedding dim
#define NTRAIN  50000    // train rows
#define NATTR   8        // attributes
#define CAP     1024     // per-b matched-sim buffer (mean ~130, huge margin)
#define KNB     5        // top-k
#define ROWS_PB 8        // rows per block (1 warp matches 1 row)
#define PMAX    256      // block-local pair list cap (mean ~5.3, P(>256)~0)

// ---------------- device scratch (no allocations allowed) ----------------
// g_count is zero at static init; topk_kernel re-zeroes it after reading -> replay-safe.
__device__ int                g_count[BQ];     // matched count per query
__device__ float              g_sims[BQ * CAP];// matched (dot * inv_row) per query
__device__ float              g_loss[BQ];      // per-query loss contribution
__device__ unsigned long long g_done;          // monotonic completion counter (no reset)

// ---------------- K1: match (warp/row) + pair-parallel sparse dots ----------------
__global__ void __launch_bounds__(256, 4) match_kernel(const float* __restrict__ emb,
                                                       const int* __restrict__ attr,
                                                       const float* __restrict__ z,
                                                       const int* __restrict__ tattr) {
    __shared__ unsigned       s_ptgt[BQ];
    __shared__ unsigned short s_pairs[PMAX];   // (row_local << 8) | b
    __shared__ int            s_np;

    int t = threadIdx.x, w = t >> 5, lane = t & 31;

    // pack all 256 targets (one per thread; tattr is 8 KB, L2-hot)
    {
        unsigned p = 0;
        const int* a = tattr + t * NATTR;
        #pragma unroll
        for (int i = 0; i < NATTR; i++) p |= ((unsigned)a[i] & 3u) << (2 * i);
        s_ptgt[t] = p;
    }
    if (t == 0) s_np = 0;
    __syncthreads();

    // ---- phase A: each warp tests its row against all 256 targets ----
    int n = blockIdx.x * ROWS_PB + w;
    if (n < NTRAIN) {
        // pack row attrs (lanes 0..7 contribute one 2-bit field each, OR-reduce)
        unsigned p = 0;
        if (lane < NATTR) p = ((unsigned)attr[(size_t)n * NATTR + lane] & 3u) << (2 * lane);
        #pragma unroll
        for (int o = 16; o; o >>= 1) p |= __shfl_xor_sync(0xffffffffu, p, o);

        // <=1 mismatching 2-bit field  <=>  match_score >= 7
        #pragma unroll
        for (int g = 0; g < BQ; g += 32) {
            unsigned x = p ^ s_ptgt[g + lane];
            unsigned y = (x | (x >> 1)) & 0x5555u;
            bool hit = (__popc(y) <= 1);
            unsigned m = __ballot_sync(0xffffffffu, hit);
            if (m) {
                int base = 0;
                if (lane == 0) base = atomicAdd(&s_np, __popc(m));
                base = __shfl_sync(0xffffffffu, base, 0);
                if (hit) {
                    int pos = base + __popc(m & ((1u << lane) - 1u));
                    if (pos < PMAX)
                        s_pairs[pos] = (unsigned short)((w << 8) | (g + lane));
                }
            }
        }
    }
    __syncthreads();
    int np = s_np < PMAX ? s_np : PMAX;

    // ---- phase B: pairs distributed across ALL 8 warps (high MLP) ----
    for (int j = w; j < np; j += ROWS_PB) {
        int pr  = s_pairs[j];
        int row = blockIdx.x * ROWS_PB + (pr >> 8);
        int b   = pr & 255;

        // 8 independent LDG.128 per lane: row tile + z tile issued together
        const float4* rr = (const float4*)(emb + (size_t)row * D);
        const float4* zr = (const float4*)(z + (size_t)b * D);
        float4 r0 = rr[lane];      float4 z0 = zr[lane];
        float4 r1 = rr[lane + 32]; float4 z1 = zr[lane + 32];
        float4 r2 = rr[lane + 64]; float4 z2 = zr[lane + 64];
        float4 r3 = rr[lane + 96]; float4 z3 = zr[lane + 96];

        float ss = r0.x*r0.x + r0.y*r0.y + r0.z*r0.z + r0.w*r0.w
                 + r1.x*r1.x + r1.y*r1.y + r1.z*r1.z + r1.w*r1.w
                 + r2.x*r2.x + r2.y*r2.y + r2.z*r2.z + r2.w*r2.w
                 + r3.x*r3.x + r3.y*r3.y + r3.z*r3.z + r3.w*r3.w;
        float d  = r0.x*z0.x + r0.y*z0.y + r0.z*z0.z + r0.w*z0.w
                 + r1.x*z1.x + r1.y*z1.y + r1.z*z1.z + r1.w*z1.w
                 + r2.x*z2.x + r2.y*z2.y + r2.z*z2.z + r2.w*z2.w
                 + r3.x*z3.x + r3.y*z3.y + r3.z*z3.z + r3.w*z3.w;
        #pragma unroll
        for (int o = 16; o; o >>= 1) {
            ss += __shfl_xor_sync(0xffffffffu, ss, o);
            d  += __shfl_xor_sync(0xffffffffu, d,  o);
        }
        if (lane == 0) {
            float inv = 1.0f / fmaxf(sqrtf(ss), 1e-12f);  // row inv-norm (F.normalize eps)
            int pos = atomicAdd(&g_count[b], 1);
            if (pos < CAP) g_sims[(size_t)b * CAP + pos] = d * inv;
        }
    }
}

// ---------------- K2: per-b inv_z + top-5 + fused deterministic reduce + counter reset ----
__global__ void __launch_bounds__(32) topk_kernel(const float* __restrict__ z,
                                                  float* __restrict__ out) {
    __shared__ float sv[CAP];
    int b = blockIdx.x;
    int lane = threadIdx.x;

    // inv-norm of z[b] (2 KB, L2-hot). invz > 0 preserves top-k ordering; applied at end.
    const float4* zr = (const float4*)(z + (size_t)b * D);
    float4 z0 = zr[lane], z1 = zr[lane + 32], z2 = zr[lane + 64], z3 = zr[lane + 96];
    float ss = z0.x*z0.x + z0.y*z0.y + z0.z*z0.z + z0.w*z0.w
             + z1.x*z1.x + z1.y*z1.y + z1.z*z1.z + z1.w*z1.w
             + z2.x*z2.x + z2.y*z2.y + z2.z*z2.z + z2.w*z2.w
             + z3.x*z3.x + z3.y*z3.y + z3.z*z3.z + z3.w*z3.w;
    #pragma unroll
    for (int o = 16; o; o >>= 1) ss += __shfl_xor_sync(0xffffffffu, ss, o);
    float invz = 1.0f / fmaxf(sqrtf(ss), 1e-12f);

    int cnt = g_count[b];
    if (cnt > CAP) cnt = CAP;
    for (int i = lane; i < cnt; i += 32) sv[i] = g_sims[(size_t)b * CAP + i];
    if (lane == 0) g_count[b] = 0;                 // reset for next graph replay
    __syncwarp();

    // 5 argmax passes; masked_sim has 49k+ zeros so each selection clamps at 0
    float sum5 = 0.0f;
    #pragma unroll
    for (int k = 0; k < KNB; k++) {
        float mx = -1e30f; int mi = -1;
        for (int i = lane; i < cnt; i += 32) {
            float v = sv[i];
            if (v > mx) { mx = v; mi = i; }
        }
        float bmx = mx;
        #pragma unroll
        for (int o = 16; o; o >>= 1) bmx = fmaxf(bmx, __shfl_xor_sync(0xffffffffu, bmx, o));
        sum5 += fmaxf(bmx, 0.0f);
        unsigned has = __ballot_sync(0xffffffffu, (mx == bmx) && (mi >= 0));
        if (has) {
            int owner = (int)__ffs(has) - 1;
            if (lane == owner) sv[mi] = -1e30f;     // remove exactly one instance
        }
        __syncwarp();
    }

    if (lane == 0) {
        float per = 1.0f - (invz * sum5) / (float)KNB;
        g_loss[b] = (cnt >= KNB) ? per : 0.0f;
        __threadfence();
    }
    __syncwarp();

    // last block (monotonic counter, no reset needed) sums g_loss in fixed order
    int last = 0;
    if (lane == 0) {
        unsigned long long my = atomicAdd(&g_done, 1ULL);
        last = ((my % BQ) == BQ - 1) ? 1 : 0;
    }
    last = __shfl_sync(0xffffffffu, last, 0);
    if (last) {
        __threadfence();
        float s = 0.0f;
        #pragma unroll
        for (int i = 0; i < BQ / 32; i++)           // fixed order: deterministic
            s += __ldcg(&g_loss[lane + i * 32]);
        #pragma unroll
        for (int o = 16; o; o >>= 1) s += __shfl_xor_sync(0xffffffffu, s, o);
        if (lane == 0) out[0] = s / (float)BQ;
    }
}

extern "C" void kernel_launch(void* const* d_in, const int* in_sizes, int n_in,
                              void* d_out, int out_size) {
    const float* z     = (const float*)d_in[0];   // z_flowed         [256,512]   f32
    const int*   tattr = (const int*)d_in[1];     // target_attrs     [256,8]     i32
    const float* emb   = (const float*)d_in[2];   // train_embeddings [50000,512] f32
    const int*   attr  = (const int*)d_in[3];     // train_attributes [50000,8]   i32
    float*       out   = (float*)d_out;

    match_kernel<<<(NTRAIN + ROWS_PB - 1) / ROWS_PB, 256>>>(emb, attr, z, tattr);
    topk_kernel<<<BQ, 32>>>(z, out);
}

// round 10
// speedup vs baseline: 1.6744x; 1.6744x over previous
#include <cuda_runtime.h>
#include <math.h>

#define BQ      256      // batch (queries)
#define D       512      // embedding dim
#define NTRAIN  50000    // train rows
#define NATTR   8        // attributes
#define CAP     1024     // per-b matched-sim buffer (mean ~130, huge margin)
#define KNB     5        // top-k
#define NBLK_M  592      // 4 blocks/SM x 148 SMs
#define RPB     85       // rows per block (592*85 = 50320 >= 50000)
#define PMAX    384      // block pair-list cap (mean ~56, +26 sigma margin)

// ---------------- device scratch (no allocations allowed) ----------------
// g_count zero at static init; topk re-zeroes after reading -> graph-replay-safe.
__device__ int                g_count[BQ];      // matched count per query
__device__ float              g_sims[BQ * CAP]; // matched (dot * inv_row) per query
__device__ float              g_loss[BQ];       // per-query loss contribution
__device__ unsigned long long g_done;           // monotonic completion counter (no reset)

// ---------------- K1: match (warp/row, amortized targets) + pair-parallel dots ----------------
__global__ void __launch_bounds__(256) match_kernel(const float* __restrict__ emb,
                                                    const int* __restrict__ attr,
                                                    const float* __restrict__ z,
                                                    const int* __restrict__ tattr) {
    __shared__ unsigned       s_ptgt[BQ];
    __shared__ unsigned short s_pairs[PMAX];    // (row_local << 8) | b
    __shared__ int            s_np;

    int t = threadIdx.x, w = t >> 5, lane = t & 31;

    // pack all 256 targets ONCE per block (one per thread)
    {
        unsigned p = 0;
        const int* a = tattr + t * NATTR;
        #pragma unroll
        for (int i = 0; i < NATTR; i++) p |= ((unsigned)a[i] & 3u) << (2 * i);
        s_ptgt[t] = p;
    }
    if (t == 0) s_np = 0;
    __syncthreads();

    int base = blockIdx.x * RPB;

    // ---- phase A: warps stride over this block's ~85 rows ----
    for (int r = w; r < RPB; r += 8) {
        int n = base + r;
        if (n >= NTRAIN) break;

        // pack row attrs (lanes 0..7 contribute one 2-bit field each, OR-reduce)
        unsigned p = 0;
        if (lane < NATTR) p = ((unsigned)attr[(size_t)n * NATTR + lane] & 3u) << (2 * lane);
        #pragma unroll
        for (int o = 16; o; o >>= 1) p |= __shfl_xor_sync(0xffffffffu, p, o);

        // <=1 mismatching 2-bit field  <=>  match_score >= 7
        #pragma unroll
        for (int g = 0; g < BQ; g += 32) {
            unsigned x = p ^ s_ptgt[g + lane];
            unsigned y = (x | (x >> 1)) & 0x5555u;
            bool hit = (__popc(y) <= 1);
            unsigned m = __ballot_sync(0xffffffffu, hit);
            if (m) {                             // rare (~0.66 hits per row total)
                int bpos = 0;
                if (lane == 0) bpos = atomicAdd(&s_np, __popc(m));
                bpos = __shfl_sync(0xffffffffu, bpos, 0);
                if (hit) {
                    int pos = bpos + __popc(m & ((1u << lane) - 1u));
                    if (pos < PMAX)
                        s_pairs[pos] = (unsigned short)((r << 8) | (g + lane));
                }
            }
        }
    }
    __syncthreads();
    int np = s_np < PMAX ? s_np : PMAX;

    // ---- phase B: pairs distributed across all 8 warps (8 indep LDG.128 each) ----
    for (int j = w; j < np; j += 8) {
        int pr  = s_pairs[j];
        int row = base + (pr >> 8);
        int b   = pr & 255;

        const float4* rr = (const float4*)(emb + (size_t)row * D);
        const float4* zr = (const float4*)(z + (size_t)b * D);
        float4 r0 = rr[lane];      float4 z0 = zr[lane];
        float4 r1 = rr[lane + 32]; float4 z1 = zr[lane + 32];
        float4 r2 = rr[lane + 64]; float4 z2 = zr[lane + 64];
        float4 r3 = rr[lane + 96]; float4 z3 = zr[lane + 96];

        float ss = r0.x*r0.x + r0.y*r0.y + r0.z*r0.z + r0.w*r0.w
                 + r1.x*r1.x + r1.y*r1.y + r1.z*r1.z + r1.w*r1.w
                 + r2.x*r2.x + r2.y*r2.y + r2.z*r2.z + r2.w*r2.w
                 + r3.x*r3.x + r3.y*r3.y + r3.z*r3.z + r3.w*r3.w;
        float d  = r0.x*z0.x + r0.y*z0.y + r0.z*z0.z + r0.w*z0.w
                 + r1.x*z1.x + r1.y*z1.y + r1.z*z1.z + r1.w*z1.w
                 + r2.x*z2.x + r2.y*z2.y + r2.z*z2.z + r2.w*z2.w
                 + r3.x*z3.x + r3.y*z3.y + r3.z*z3.z + r3.w*z3.w;
        #pragma unroll
        for (int o = 16; o; o >>= 1) {
            ss += __shfl_xor_sync(0xffffffffu, ss, o);
            d  += __shfl_xor_sync(0xffffffffu, d,  o);
        }
        if (lane == 0) {
            float inv = 1.0f / fmaxf(sqrtf(ss), 1e-12f);  // row inv-norm (F.normalize eps)
            int pos = atomicAdd(&g_count[b], 1);
            if (pos < CAP) g_sims[(size_t)b * CAP + pos] = d * inv;
        }
    }
}

// ---------------- K2: 128-thread top-5 + fused deterministic reduce + counter reset ----
__global__ void __launch_bounds__(128) topk_kernel(const float* __restrict__ z,
                                                   float* __restrict__ out) {
    __shared__ float sv[CAP];
    __shared__ float s_red[4];
    __shared__ int   s_sel;
    int b = blockIdx.x;
    int t = threadIdx.x, w = t >> 5, lane = t & 31;

    // inv-norm of z[b] (2 KB, L2-hot). invz > 0 preserves top-k order; applied at end.
    float4 zv = ((const float4*)(z + (size_t)b * D))[t];
    float ss = zv.x*zv.x + zv.y*zv.y + zv.z*zv.z + zv.w*zv.w;
    #pragma unroll
    for (int o = 16; o; o >>= 1) ss += __shfl_xor_sync(0xffffffffu, ss, o);
    if (lane == 0) s_red[w] = ss;

    int cnt = g_count[b];
    if (cnt > CAP) cnt = CAP;
    for (int i = t; i < cnt; i += 128) sv[i] = g_sims[(size_t)b * CAP + i];
    if (t == 0) g_count[b] = 0;                     // reset for next graph replay
    __syncthreads();
    float invz = 1.0f / fmaxf(sqrtf(s_red[0] + s_red[1] + s_red[2] + s_red[3]), 1e-12f);

    // 5 block-wide argmax passes; 49k+ zeros in masked_sim -> clamp each pick at 0.
    float sum5 = 0.0f;
    #pragma unroll
    for (int k = 0; k < KNB; k++) {
        float mx = -1e30f;
        for (int i = t; i < cnt; i += 128) mx = fmaxf(mx, sv[i]);
        #pragma unroll
        for (int o = 16; o; o >>= 1) mx = fmaxf(mx, __shfl_xor_sync(0xffffffffu, mx, o));
        if (lane == 0) s_red[w] = mx;
        if (t == 0) s_sel = 0x7fffffff;
        __syncthreads();
        float bmx = fmaxf(fmaxf(s_red[0], s_red[1]), fmaxf(s_red[2], s_red[3]));
        sum5 += fmaxf(bmx, 0.0f);
        // deterministic owner: min index holding bmx
        for (int i = t; i < cnt; i += 128)
            if (sv[i] == bmx) atomicMin(&s_sel, i);
        __syncthreads();
        if (t == 0 && s_sel != 0x7fffffff) sv[s_sel] = -1e30f;  // remove one instance
        __syncthreads();
    }

    if (t == 0) {
        float per = 1.0f - (invz * sum5) / (float)KNB;
        g_loss[b] = (cnt >= KNB) ? per : 0.0f;
        __threadfence();
    }
    __syncthreads();

    // last block (monotonic counter) sums g_loss in fixed order -> deterministic
    if (w == 0) {
        int last = 0;
        if (lane == 0) {
            unsigned long long my = atomicAdd(&g_done, 1ULL);
            last = ((my % BQ) == BQ - 1) ? 1 : 0;
        }
        last = __shfl_sync(0xffffffffu, last, 0);
        if (last) {
            __threadfence();
            float s = 0.0f;
            #pragma unroll
            for (int i = 0; i < BQ / 32; i++)
                s += __ldcg(&g_loss[lane + i * 32]);
            #pragma unroll
            for (int o = 16; o; o >>= 1) s += __shfl_xor_sync(0xffffffffu, s, o);
            if (lane == 0) out[0] = s / (float)BQ;
        }
    }
}

extern "C" void kernel_launch(void* const* d_in, const int* in_sizes, int n_in,
                              void* d_out, int out_size) {
    const float* z     = (const float*)d_in[0];   // z_flowed         [256,512]   f32
    const int*   tattr = (const int*)d_in[1];     // target_attrs     [256,8]     i32
    const float* emb   = (const float*)d_in[2];   // train_embeddings [50000,512] f32
    const int*   attr  = (const int*)d_in[3];     // train_attributes [50000,8]   i32
    float*       out   = (float*)d_out;

    match_kernel<<<NBLK_M, 256>>>(emb, attr, z, tattr);
    topk_kernel<<<BQ, 128>>>(z, out);
}

// round 11
// speedup vs baseline: 1.9404x; 1.1589x over previous
#include <cuda_runtime.h>
#include <math.h>

#define BQ      256      // batch (queries)
#define D       512      // embedding dim
#define NTRAIN  50000    // train rows
#define NATTR   8        // attributes
#define CAP     1024     // per-b matched-sim buffer (mean ~130, huge margin)
#define KNB     5        // top-k
#define NBLK_M  592      // 4 blocks/SM x 148 SMs
#define RPB     85       // rows per block (592*85 = 50320 >= 50000)
#define PMAX    384      // block pair-list cap (mean ~56, +26 sigma margin)

// ---------------- device scratch (no allocations allowed) ----------------
// g_count zero at static init; topk re-zeroes after reading -> graph-replay-safe.
__device__ int                g_count[BQ];      // matched count per query
__device__ float              g_sims[BQ * CAP]; // matched (dot * inv_row) per query
__device__ float              g_loss[BQ];       // per-query loss contribution
__device__ unsigned long long g_done;           // monotonic completion counter (no reset)

// ---------------- K1: bit-sliced match + pair-parallel sparse dots ----------------
__global__ void __launch_bounds__(256) match_kernel(const float* __restrict__ emb,
                                                    const int* __restrict__ attr,
                                                    const float* __restrict__ z,
                                                    const int* __restrict__ tattr) {
    __shared__ unsigned       s_mask[NATTR * 3 * 8];  // [attr][val][word]: targets with attr==val
    __shared__ unsigned short s_pairs[PMAX];          // (row_local << 8) | b
    __shared__ int            s_np;

    int t = threadIdx.x, w = t >> 5, lane = t & 31;

    // ---- build value-indexed target bitmasks (warp w = target word w) ----
    {
        int av[NATTR];
        const int* a = tattr + t * NATTR;
        #pragma unroll
        for (int i = 0; i < NATTR; i++) av[i] = a[i];
        #pragma unroll
        for (int ai = 0; ai < NATTR; ai++) {
            #pragma unroll
            for (int v = 0; v < 3; v++) {
                unsigned m = __ballot_sync(0xffffffffu, av[ai] == v);
                if (lane == 0) s_mask[(ai * 3 + v) * 8 + w] = m;
            }
        }
    }
    if (t == 0) s_np = 0;
    __syncthreads();

    int base = blockIdx.x * RPB;
    int q = lane >> 3, oct = lane & 7;      // lane -> (row-in-quad, target-word)

    // ---- phase A: each warp tests 4 rows per iteration (bit-sliced, no ballots) ----
    for (int r0 = w * 4; r0 < RPB; r0 += 32) {
        int rl = r0 + q;                    // row local to block
        int n = base + rl;
        bool rowok = (rl < RPB) && (n < NTRAIN);
        // coalesced 128B load: 4 rows x 8 attrs
        int val = rowok ? attr[(size_t)n * NATTR + oct] : 0;

        // pack row attrs within each octet (all 8 lanes of octet end with full p)
        unsigned p = ((unsigned)val & 3u) << (2 * oct);
        p |= __shfl_xor_sync(0xffffffffu, p, 1);
        p |= __shfl_xor_sync(0xffffffffu, p, 2);
        p |= __shfl_xor_sync(0xffffffffu, p, 4);

        // bit-sliced mismatch count over this lane's 32 targets
        unsigned seen = 0, two = 0;
        #pragma unroll
        for (int ai = 0; ai < NATTR; ai++) {
            unsigned v = (p >> (2 * ai)) & 3u;
            unsigned m = ~s_mask[(ai * 3 + v) * 8 + oct];   // mismatching targets
            two  |= seen & m;
            seen |= m;
        }
        unsigned hit = rowok ? ~two : 0u;   // <=1 mismatch <=> match_score >= 7

        // warp compaction of hit bits into the block pair list
        int c = __popc(hit);
        int pre = c;
        #pragma unroll
        for (int o = 1; o < 32; o <<= 1) {
            int u = __shfl_up_sync(0xffffffffu, pre, o);
            if (lane >= o) pre += u;
        }
        int tot = __shfl_sync(0xffffffffu, pre, 31);
        if (tot) {
            int bpos = 0;
            if (lane == 31) bpos = atomicAdd(&s_np, tot);
            bpos = __shfl_sync(0xffffffffu, bpos, 31);
            int idx = bpos + pre - c;
            unsigned rem = hit;
            while (rem) {
                int bit = __ffs(rem) - 1;
                rem &= rem - 1;
                if (idx < PMAX)
                    s_pairs[idx] = (unsigned short)((rl << 8) | (oct * 32 + bit));
                idx++;
            }
        }
    }
    __syncthreads();
    int np = s_np < PMAX ? s_np : PMAX;

    // ---- phase B: pairs distributed across all 8 warps (8 indep LDG.128 each) ----
    for (int j = w; j < np; j += 8) {
        int pr  = s_pairs[j];
        int row = base + (pr >> 8);
        int b   = pr & 255;

        const float4* rr = (const float4*)(emb + (size_t)row * D);
        const float4* zr = (const float4*)(z + (size_t)b * D);
        float4 r0 = rr[lane];      float4 z0 = zr[lane];
        float4 r1 = rr[lane + 32]; float4 z1 = zr[lane + 32];
        float4 r2 = rr[lane + 64]; float4 z2 = zr[lane + 64];
        float4 r3 = rr[lane + 96]; float4 z3 = zr[lane + 96];

        float ss = r0.x*r0.x + r0.y*r0.y + r0.z*r0.z + r0.w*r0.w
                 + r1.x*r1.x + r1.y*r1.y + r1.z*r1.z + r1.w*r1.w
                 + r2.x*r2.x + r2.y*r2.y + r2.z*r2.z + r2.w*r2.w
                 + r3.x*r3.x + r3.y*r3.y + r3.z*r3.z + r3.w*r3.w;
        float d  = r0.x*z0.x + r0.y*z0.y + r0.z*z0.z + r0.w*z0.w
                 + r1.x*z1.x + r1.y*z1.y + r1.z*z1.z + r1.w*z1.w
                 + r2.x*z2.x + r2.y*z2.y + r2.z*z2.z + r2.w*z2.w
                 + r3.x*z3.x + r3.y*z3.y + r3.z*z3.z + r3.w*z3.w;
        #pragma unroll
        for (int o = 16; o; o >>= 1) {
            ss += __shfl_xor_sync(0xffffffffu, ss, o);
            d  += __shfl_xor_sync(0xffffffffu, d,  o);
        }
        if (lane == 0) {
            float inv = 1.0f / fmaxf(sqrtf(ss), 1e-12f);  // row inv-norm (F.normalize eps)
            int pos = atomicAdd(&g_count[b], 1);
            if (pos < CAP) g_sims[(size_t)b * CAP + pos] = d * inv;
        }
    }
}

// ---------------- K2: warp-per-query register top-5 + fused deterministic reduce ----
__global__ void __launch_bounds__(256) topk_kernel(const float* __restrict__ z,
                                                   float* __restrict__ out) {
    int t = threadIdx.x, w = t >> 5, lane = t & 31;
    int b = blockIdx.x * 8 + w;                      // 32 blocks x 8 warps = 256 queries

    // inv-norm of z[b] (2 KB, L2-hot). invz > 0 preserves top-k order; applied at end.
    const float4* zr = (const float4*)(z + (size_t)b * D);
    float4 z0 = zr[lane], z1 = zr[lane + 32], z2 = zr[lane + 64], z3 = zr[lane + 96];
    float ss = z0.x*z0.x + z0.y*z0.y + z0.z*z0.z + z0.w*z0.w
             + z1.x*z1.x + z1.y*z1.y + z1.z*z1.z + z1.w*z1.w
             + z2.x*z2.x + z2.y*z2.y + z2.z*z2.z + z2.w*z2.w
             + z3.x*z3.x + z3.y*z3.y + z3.z*z3.z + z3.w*z3.w;
    #pragma unroll
    for (int o = 16; o; o >>= 1) ss += __shfl_xor_sync(0xffffffffu, ss, o);
    float invz = 1.0f / fmaxf(sqrtf(ss), 1e-12f);

    int cnt = g_count[b];
    if (cnt > CAP) cnt = CAP;
    if (lane == 0) g_count[b] = 0;                   // reset for next graph replay

    // per-lane sorted top-5 in registers over strided elements
    float t0 = -1e30f, t1 = -1e30f, t2 = -1e30f, t3 = -1e30f, t4 = -1e30f;
    for (int i = lane; i < cnt; i += 32) {
        float v = g_sims[(size_t)b * CAP + i];
        if (v > t4) {
            if      (v > t0) { t4=t3; t3=t2; t2=t1; t1=t0; t0=v; }
            else if (v > t1) { t4=t3; t3=t2; t2=t1; t1=v; }
            else if (v > t2) { t4=t3; t3=t2; t2=v; }
            else if (v > t3) { t4=t3; t3=v; }
            else             { t4=v; }
        }
    }

    // 5 merge rounds: warp-max of heads, lowest-lane owner pops (deterministic).
    // masked_sim has 49k+ zeros -> each selection clamps at 0.
    float sum5 = 0.0f;
    #pragma unroll
    for (int k = 0; k < KNB; k++) {
        float m = t0;
        #pragma unroll
        for (int o = 16; o; o >>= 1) m = fmaxf(m, __shfl_xor_sync(0xffffffffu, m, o));
        sum5 += fmaxf(m, 0.0f);
        unsigned msk = __ballot_sync(0xffffffffu, t0 == m);
        int owner = (int)__ffs(msk) - 1;
        if (lane == owner) { t0=t1; t1=t2; t2=t3; t3=t4; t4=-1e30f; }
    }

    if (lane == 0) {
        float per = 1.0f - (invz * sum5) / (float)KNB;
        g_loss[b] = (cnt >= KNB) ? per : 0.0f;
        __threadfence();
    }
    __syncwarp();

    // last warp (monotonic counter) sums g_loss in fixed order -> deterministic
    int last = 0;
    if (lane == 0) {
        unsigned long long my = atomicAdd(&g_done, 1ULL);
        last = ((my % BQ) == BQ - 1) ? 1 : 0;
    }
    last = __shfl_sync(0xffffffffu, last, 0);
    if (last) {
        __threadfence();
        float s = 0.0f;
        #pragma unroll
        for (int i = 0; i < BQ / 32; i++)            // fixed order: deterministic
            s += __ldcg(&g_loss[lane + i * 32]);
        #pragma unroll
        for (int o = 16; o; o >>= 1) s += __shfl_xor_sync(0xffffffffu, s, o);
        if (lane == 0) out[0] = s / (float)BQ;
    }
}

extern "C" void kernel_launch(void* const* d_in, const int* in_sizes, int n_in,
                              void* d_out, int out_size) {
    const float* z     = (const float*)d_in[0];   // z_flowed         [256,512]   f32
    const int*   tattr = (const int*)d_in[1];     // target_attrs     [256,8]     i32
    const float* emb   = (const float*)d_in[2];   // train_embeddings [50000,512] f32
    const int*   attr  = (const int*)d_in[3];     // train_attributes [50000,8]   i32
    float*       out   = (float*)d_out;

    match_kernel<<<NBLK_M, 256>>>(emb, attr, z, tattr);
    topk_kernel<<<BQ / 8, 256>>>(z, out);
}